// round 16
// baseline (speedup 1.0000x reference)
#include <cuda_runtime.h>
#include <cuda_bf16.h>
#include <cstdint>
#include <cstddef>

#define N_TOK   131072
#define DIM     64
#define KCODES  1024
#define KHALF   512
#define QBLOCKS 512
#define MGN     1e-3f            // screen margin (>=3x bf16 mma+storage error)

// Output layout (float32, flattened tuple order)
#define OUT_Q    ((size_t)1)
#define OUT_PERP ((size_t)1 + (size_t)N_TOK * DIM)
#define OUT_IDX  ((size_t)2 + (size_t)N_TOK * DIM)

typedef unsigned long long u64;

// smem map: A @0 (128x144B) | B @18432 (512x144B) | dots @92160 (128x1040B)
#define RS      144
#define DRS     1040
#define SM_A    0
#define SM_B    18432
#define SM_D    92160
#define SMEM_SZ (SM_D + 128 * DRS)     // 225280

// ---------------- device scratch (no allocations allowed) ----------------
__device__ float    g_e2[KCODES];
__device__ int      g_idx[N_TOK];
__device__ int      g_counts[KCODES];
__device__ double   g_block_sse[QBLOCKS];
__device__ uint32_t g_xbf[N_TOK * DIM / 2];    // bf16x2-packed inputs
__device__ uint32_t g_cbbf[KCODES * DIM / 2];  // bf16x2-packed codebook

// ---------------- packed f32x2 helpers (frozen exact-rescore path) -------
__device__ __forceinline__ void ffma2(u64& d, u64 a, u64 b) {
    asm("fma.rn.f32x2 %0, %1, %2, %0;" : "+l"(d) : "l"(a), "l"(b));
}
__device__ __forceinline__ float2 unpack2(u64 v) {
    float2 f; asm("mov.b64 {%0, %1}, %2;" : "=f"(f.x), "=f"(f.y) : "l"(v)); return f;
}
__device__ __forceinline__ uint32_t bfpack(float lo, float hi) {
    uint32_t r; asm("cvt.rn.bf16x2.f32 %0, %1, %2;" : "=r"(r) : "f"(hi), "f"(lo));
    return r;
}

// ---------------- warp-MMA helpers (plain-target PTX, sm_80+) ------------
__device__ __forceinline__ void ldsm4(uint32_t* r, uint32_t addr) {
    asm volatile("ldmatrix.sync.aligned.m8n8.x4.shared.b16 {%0,%1,%2,%3}, [%4];"
        : "=r"(r[0]), "=r"(r[1]), "=r"(r[2]), "=r"(r[3]) : "r"(addr));
}
__device__ __forceinline__ void mma16816(float* d, const uint32_t* a,
                                         const uint32_t* b, const float* c) {
    asm volatile("mma.sync.aligned.m16n8k16.row.col.f32.bf16.bf16.f32 "
        "{%0,%1,%2,%3}, {%4,%5,%6,%7}, {%8,%9}, {%10,%11,%12,%13};"
        : "=f"(d[0]), "=f"(d[1]), "=f"(d[2]), "=f"(d[3])
        : "r"(a[0]), "r"(a[1]), "r"(a[2]), "r"(a[3]), "r"(b[0]), "r"(b[1]),
          "f"(c[0]), "f"(c[1]), "f"(c[2]), "f"(c[3]));
}

// ---------------- cp.async helpers ---------------------------------------
__device__ __forceinline__ void cp_async16(void* smem_dst, const void* gsrc) {
    uint32_t s = (uint32_t)__cvta_generic_to_shared(smem_dst);
    asm volatile("cp.async.cg.shared.global [%0], [%1], 16;" :: "r"(s), "l"(gsrc));
}
__device__ __forceinline__ void cp_commit() {
    asm volatile("cp.async.commit_group;");
}
template <int N>
__device__ __forceinline__ void cp_wait() {
    asm volatile("cp.async.wait_group %0;" :: "n"(N));
}

// ---------------- kernel 0: prep (e2 frozen, counts, bf16 convert) -------
__global__ void vq_prep_kernel(const float* __restrict__ x, const float* __restrict__ cb) {
    const int i = blockIdx.x * 256 + threadIdx.x;      // [0, N_TOK)

    const float2* xp = reinterpret_cast<const float2*>(x);
    #pragma unroll 4
    for (int j = 0; j < 32; ++j) {
        int p = j * N_TOK + i;
        float2 v = xp[p];
        g_xbf[p] = bfpack(v.x, v.y);
    }

    if (i < KCODES) {
        const float* row = cb + (size_t)i * DIM;
        float s0 = 0.f, s1 = 0.f, s2 = 0.f, s3 = 0.f;   // FROZEN e2 order
        #pragma unroll
        for (int j = 0; j < DIM; j += 4) {
            s0 = fmaf(row[j+0], row[j+0], s0);
            s1 = fmaf(row[j+1], row[j+1], s1);
            s2 = fmaf(row[j+2], row[j+2], s2);
            s3 = fmaf(row[j+3], row[j+3], s3);
        }
        g_e2[i] = (s0 + s1) + (s2 + s3);
        g_counts[i] = 0;
        const float2* cr = reinterpret_cast<const float2*>(row);
        #pragma unroll
        for (int w = 0; w < 32; ++w) {
            float2 v = cr[w];
            g_cbbf[i * 32 + w] = bfpack(v.x, v.y);
        }
    }
}

// ---------------- kernel 1: 1-pass bf16 HMMA screen + exact rescore ------
// 1024 CTAs x 128 thr; CTA owns 128 tokens x all 1024 codes (2 halves,
// B smem reused; half-1 B prefetched via cp.async during half-0 scan).
// MMA pass writes dots (bf16) to smem; scan per thread=token finds max and
// inline-rescores every code with dot > max - MGN using the FROZEN fp32
// chain, ascending code order, strict '<' (reference argmin semantics).
__global__ void __launch_bounds__(128)
vq_argmin_kernel(const float* __restrict__ x, const float* __restrict__ cb,
                 float* __restrict__ dout) {
    extern __shared__ __align__(128) char smem[];
    const int tid = threadIdx.x;
    const int wid = tid >> 5;
    const int lid = tid & 31;
    const uint32_t sb = (uint32_t)__cvta_generic_to_shared(smem);

    // stage B half 0 via cp.async (512 rows x 8 x 16B chunks)
    #pragma unroll
    for (int j = 0; j < 32; ++j) {
        int flat = j * 128 + tid;
        int row = flat >> 3, ch = flat & 7;
        cp_async16(smem + SM_B + row * RS + ch * 16,
                   (const char*)g_cbbf + (size_t)row * 128 + ch * 16);
    }
    cp_commit();

    // stage A: 128 token rows x 32 bf16x2 words (plain, overlaps cp.async)
    {
        const uint32_t* src = g_xbf + (size_t)blockIdx.x * 128 * 32;
        #pragma unroll
        for (int j = 0; j < 32; ++j) {
            int flat = j * 128 + tid;
            int row = flat >> 5, w = flat & 31;
            *reinterpret_cast<uint32_t*>(smem + SM_A + row * RS + w * 4) = src[flat];
        }
    }
    cp_wait<0>();
    __syncthreads();

    // Preload A fragments: 2 m-blocks x 4 k-steps x 4 regs (proven mapping)
    uint32_t afr[2][4][4];
    {
        const int rl = lid & 15;
        const int kh = ((lid >> 4) & 1) * 8;
        #pragma unroll
        for (int mb = 0; mb < 2; ++mb) {
            int mbase = wid * 32 + mb * 16;
            #pragma unroll
            for (int s = 0; s < 4; ++s)
                ldsm4(afr[mb][s], sb + SM_A + (mbase + rl) * RS + (s * 16 + kh) * 2);
        }
    }

    // FROZEN per-token data for exact rescore
    const int token = blockIdx.x * 128 + tid;
    u64 px[DIM / 2];
    {
        const ulonglong2* rx = reinterpret_cast<const ulonglong2*>(x + (size_t)token * DIM);
        #pragma unroll
        for (int i = 0; i < DIM / 4; ++i) {
            ulonglong2 v = rx[i]; px[2*i] = v.x; px[2*i+1] = v.y;
        }
    }
    float x2;
    {
        u64 qa = 0ull;
        #pragma unroll
        for (int p = 0; p < DIM / 2; ++p) ffma2(qa, px[p], px[p]);
        float2 f = unpack2(qa);
        x2 = f.x + f.y;
    }

    const int q = lid & 3;
    const int r0 = wid * 32 + (lid >> 2);
    const uint32_t brow_base = sb + SM_B + (lid & 7) * RS;
    const uint32_t bk = ((lid >> 3) * 8) * 2;

    float bestd = 3.4e38f;
    int   bi    = 0;

    #pragma unroll 1
    for (int half = 0; half < 2; ++half) {
        // ---- MMA pass: dots -> smem (bf16) ----
        #pragma unroll 2
        for (int nb = 0; nb < 64; ++nb) {
            uint32_t bfr[8];
            uint32_t br = brow_base + nb * 8 * RS;
            ldsm4(bfr + 0, br + bk);
            ldsm4(bfr + 4, br + 64 + bk);
            float c0[4] = {0.f, 0.f, 0.f, 0.f};
            float c1[4] = {0.f, 0.f, 0.f, 0.f};
            #pragma unroll
            for (int s = 0; s < 4; ++s) {
                mma16816(c0, afr[0][s], bfr + 2 * s, c0);
                mma16816(c1, afr[1][s], bfr + 2 * s, c1);
            }
            uint32_t coff = (uint32_t)(nb * 16 + q * 4);      // byte off in row
            *reinterpret_cast<uint32_t*>(smem + SM_D + (r0 +  0) * DRS + coff) = bfpack(c0[0], c0[1]);
            *reinterpret_cast<uint32_t*>(smem + SM_D + (r0 +  8) * DRS + coff) = bfpack(c0[2], c0[3]);
            *reinterpret_cast<uint32_t*>(smem + SM_D + (r0 + 16) * DRS + coff) = bfpack(c1[0], c1[1]);
            *reinterpret_cast<uint32_t*>(smem + SM_D + (r0 + 24) * DRS + coff) = bfpack(c1[2], c1[3]);
        }
        __syncthreads();

        // prefetch B half 1 while scanning half 0
        if (half == 0) {
            #pragma unroll
            for (int j = 0; j < 32; ++j) {
                int flat = j * 128 + tid;
                int row = flat >> 3, ch = flat & 7;
                cp_async16(smem + SM_B + row * RS + ch * 16,
                           (const char*)g_cbbf + (size_t)(KHALF + row) * 128 + ch * 16);
            }
            cp_commit();
        }

        // ---- scan: thread = token; sweep1 max, sweep2 inline exact ----
        const char* drow = smem + SM_D + tid * DRS;
        float mx = -3.4e38f;
        #pragma unroll 4
        for (int s = 0; s < 64; ++s) {
            uint4 v = *reinterpret_cast<const uint4*>(drow + s * 16);
            mx = fmaxf(mx, __uint_as_float(v.x << 16));
            mx = fmaxf(mx, __uint_as_float(v.x & 0xFFFF0000u));
            mx = fmaxf(mx, __uint_as_float(v.y << 16));
            mx = fmaxf(mx, __uint_as_float(v.y & 0xFFFF0000u));
            mx = fmaxf(mx, __uint_as_float(v.z << 16));
            mx = fmaxf(mx, __uint_as_float(v.z & 0xFFFF0000u));
            mx = fmaxf(mx, __uint_as_float(v.w << 16));
            mx = fmaxf(mx, __uint_as_float(v.w & 0xFFFF0000u));
        }
        const float thr = mx - MGN;

        #pragma unroll 1
        for (int s = 0; s < 64; ++s) {
            uint4 v = *reinterpret_cast<const uint4*>(drow + s * 16);
            uint32_t wds[4] = {v.x, v.y, v.z, v.w};
            #pragma unroll
            for (int u = 0; u < 4; ++u) {
                float lo = __uint_as_float(wds[u] << 16);
                float hi = __uint_as_float(wds[u] & 0xFFFF0000u);
                #pragma unroll
                for (int hb = 0; hb < 2; ++hb) {
                    float sv = hb ? hi : lo;
                    if (sv > thr) {
                        int code = half * KHALF + s * 8 + u * 2 + hb;  // ascending
                        const ulonglong2* e =
                            reinterpret_cast<const ulonglong2*>(cb + (size_t)code * DIM);
                        u64 a = 0ull;                      // FROZEN single chain
                        #pragma unroll
                        for (int p = 0; p < DIM / 4; ++p) {
                            ulonglong2 ev = e[p];
                            ffma2(a, px[2*p],   ev.x);
                            ffma2(a, px[2*p+1], ev.y);
                        }
                        float2 f = unpack2(a);
                        float d = fmaf(f.x + f.y, -2.0f, x2) + g_e2[code];
                        if (d < bestd) { bestd = d; bi = code; }
                    }
                }
            }
        }

        if (half == 0) cp_wait<0>();
        __syncthreads();      // dots consumed + B half1 visible before reuse
    }

    g_idx[token] = bi;
    dout[OUT_IDX + token] = (float)bi;
}

// ---------------- kernel 2: quantize + MSE partials + histogram ----------
__global__ void __launch_bounds__(256)
vq_quantize_kernel(const float* __restrict__ x, const float* __restrict__ cb,
                   float* __restrict__ dout) {
    __shared__ int   sbins[KCODES];
    __shared__ float swarp[8];

    for (int i = threadIdx.x; i < KCODES; i += 256) sbins[i] = 0;
    __syncthreads();

    const int dim  = threadIdx.x & 63;
    const int sub  = threadIdx.x >> 6;
    const int base = blockIdx.x * 256;

    float lsum = 0.f;
    #pragma unroll 4
    for (int it = 0; it < 64; ++it) {
        int t   = base + it * 4 + sub;
        int idx = g_idx[t];
        float qv = cb[(size_t)idx * DIM + dim];
        float xv = x[(size_t)t * DIM + dim];
        float df = qv - xv;
        dout[OUT_Q + (size_t)t * DIM + dim] = xv + df;
        lsum = fmaf(df, df, lsum);
        if (dim == 0) atomicAdd(&sbins[idx], 1);
    }

    #pragma unroll
    for (int o = 16; o > 0; o >>= 1) lsum += __shfl_down_sync(0xffffffffu, lsum, o);
    if ((threadIdx.x & 31) == 0) swarp[threadIdx.x >> 5] = lsum;
    __syncthreads();
    if (threadIdx.x == 0) {
        float s = 0.f;
        #pragma unroll
        for (int w = 0; w < 8; ++w) s += swarp[w];
        g_block_sse[blockIdx.x] = (double)s;
    }
    for (int i = threadIdx.x; i < KCODES; i += 256) {
        int c = sbins[i];
        if (c) atomicAdd(&g_counts[i], c);
    }
}

// ---------------- kernel 3: finalize loss + perplexity -------------------
__global__ void vq_finalize_kernel(float* __restrict__ dout) {
    __shared__ double sd[256];
    const int tid = threadIdx.x;

    double s = 0.0;
    for (int i = tid; i < QBLOCKS; i += 256) s += g_block_sse[i];
    sd[tid] = s;
    __syncthreads();
    #pragma unroll
    for (int o = 128; o > 0; o >>= 1) {
        if (tid < o) sd[tid] += sd[tid + o];
        __syncthreads();
    }
    double sse = sd[0];
    __syncthreads();

    double h = 0.0;
    for (int i = tid; i < KCODES; i += 256) {
        float p = (float)g_counts[i] * (1.0f / (float)N_TOK);
        h += (double)(p * logf(p + 1e-10f));
    }
    sd[tid] = h;
    __syncthreads();
    #pragma unroll
    for (int o = 128; o > 0; o >>= 1) {
        if (tid < o) sd[tid] += sd[tid + o];
        __syncthreads();
    }

    if (tid == 0) {
        float mse = (float)(sse / ((double)N_TOK * (double)DIM));
        dout[0]        = mse + 0.25f * mse;
        dout[OUT_PERP] = expf((float)(-sd[0]));
    }
}

// ---------------- launch ---------------------------------------------------
extern "C" void kernel_launch(void* const* d_in, const int* in_sizes, int n_in,
                              void* d_out, int out_size) {
    const float* x  = (const float*)d_in[0];
    const float* cb = (const float*)d_in[1];
    if (n_in >= 2 && in_sizes[0] == KCODES * DIM && in_sizes[1] == N_TOK * DIM) {
        const float* t = x; x = cb; cb = t;
    }
    float* out = (float*)d_out;

    cudaFuncSetAttribute(vq_argmin_kernel,
                         cudaFuncAttributeMaxDynamicSharedMemorySize, SMEM_SZ);

    vq_prep_kernel<<<N_TOK / 256, 256>>>(x, cb);
    vq_argmin_kernel<<<N_TOK / 128, 128, SMEM_SZ>>>(x, cb, out);
    vq_quantize_kernel<<<QBLOCKS, 256>>>(x, cb, out);
    vq_finalize_kernel<<<1, 256>>>(out);
}